// round 8
// baseline (speedup 1.0000x reference)
#include <cuda_runtime.h>
#include <cstdint>

#define VOCAB  8000
#define VPAD   8064               // padded rows in g_Wo (kept; only first VOCAB used)
#define HIDDEN 256
#define BATCH  32
#define SEQ    256
#define NROW   (SEQ * BATCH)      // 8192 output rows

// ---------------- scratch (device globals: allocation-free) ----------------
__device__ float g_WT[VOCAB * HIDDEN];   // W_ih transposed: [vocab][hidden]
__device__ float g_Xp[NROW * HIDDEN];    // gathered emb + b_ih + b_hh, rows = s*BATCH+b
__device__ float g_Y [NROW * HIDDEN];    // RNN hidden outputs (tf32-rounded)
__device__ float g_Wo[VPAD * HIDDEN];    // W_out pre-rounded to tf32
__device__ float g_hlast[BATCH * HIDDEN];// exact fp32 final hidden state

extern __shared__ unsigned char dynsm[];

// ---------------- helpers ----------------
__device__ __forceinline__ uint32_t smem_u32(const void* p) {
    uint32_t a;
    asm("{ .reg .u64 t; cvta.to.shared.u64 t, %1; cvt.u32.u64 %0, t; }"
        : "=r"(a) : "l"(p));
    return a;
}
__device__ __forceinline__ uint32_t f2tf32(float f) {
    uint32_t r; asm("cvt.rna.tf32.f32 %0, %1;" : "=r"(r) : "f"(f)); return r;
}
__device__ __forceinline__ void fma2(uint64_t& d, uint64_t a, uint64_t b) {
    asm("fma.rn.f32x2 %0, %1, %2, %0;" : "+l"(d) : "l"(a), "l"(b));
}
__device__ __forceinline__ float lo32(uint64_t v) { return __uint_as_float((uint32_t)v); }
__device__ __forceinline__ float hi32(uint64_t v) { return __uint_as_float((uint32_t)(v >> 32)); }
__device__ __forceinline__ void cpa16(uint32_t dst, const void* src) {
    asm volatile("cp.async.cg.shared.global [%0], [%1], 16;" :: "r"(dst), "l"(src));
}

// ---------------- K0: transpose W_ih (HIDDEN x VOCAB) -> g_WT ----------------
__global__ void transpose_wih(const float* __restrict__ W) {
    __shared__ float tile[32][33];
    int vx = blockIdx.x * 32 + threadIdx.x;
    int ib = blockIdx.y * 32;
    #pragma unroll
    for (int k = 0; k < 32; k += 8) {
        int i = ib + threadIdx.y + k;
        tile[threadIdx.y + k][threadIdx.x] = W[(size_t)i * VOCAB + vx];
    }
    __syncthreads();
    int i = ib + threadIdx.x;
    #pragma unroll
    for (int k = 0; k < 32; k += 8) {
        int v = blockIdx.x * 32 + threadIdx.y + k;
        g_WT[(size_t)v * HIDDEN + i] = tile[threadIdx.x][threadIdx.y + k];
    }
}

// ---------------- K1: gather embedding + fold both biases ----------------
__global__ void gather_emb(const int* __restrict__ X,
                           const float* __restrict__ b_ih,
                           const float* __restrict__ b_hh) {
    int idx = blockIdx.x * blockDim.x + threadIdx.x;
    int r = idx >> 6, q = idx & 63;
    int s = r >> 5, b = r & 31;
    int v = X[b * SEQ + s];
    float4 e  = ((const float4*)g_WT)[(size_t)v * 64 + q];
    float4 bi = ((const float4*)b_ih)[q];
    float4 bh = ((const float4*)b_hh)[q];
    e.x += bi.x + bh.x;  e.y += bi.y + bh.y;
    e.z += bi.z + bh.z;  e.w += bi.w + bh.w;
    ((float4*)g_Xp)[(size_t)r * 64 + q] = e;
}

// ---------------- K1b: pre-round W_out to tf32 ----------------
__global__ void round_wout(const float* __restrict__ Wout) {
    int i = blockIdx.x * blockDim.x + threadIdx.x;  // over VOCAB*64 float4s
    float4 f = ((const float4*)Wout)[i];
    uint4 u = make_uint4(f2tf32(f.x), f2tf32(f.y), f2tf32(f.z), f2tf32(f.w));
    ((uint4*)g_Wo)[i] = u;
}

// ---------------- K2: RNN scan v5 — LDS.128 everywhere, conflict-free ----------------
// 32 CTAs (one batch each), 1024 threads. o = warp*4 + (lane>>3), p = lane&7.
// W smem half: Ws[128 rows][8 p][36 floats] (row stride 288). LDS.128 phase
// check: 8 lanes are p=0..7 at word offset p*36+4q -> bank start 4p -> the
// eight 16B groups tile all 32 banks exactly: conflict-free.
// h: hb[2][8][36], read as ulonglong2 (4-lane broadcast, conflict-free).
// Per thread per step: 8 LDS.128 (W) + 8 LDS.128 (h) + 32 fma2 + 6 shfl.
#define WROW      288                      // 8 * 36 floats per W row
#define HB_OFF    (128 * WROW)             // hbuf: [2][8][36] floats
#define RNN_SMEM  ((HB_OFF + 2 * WROW) * 4)   // 149,760 B

__global__ void __launch_bounds__(1024, 1)
rnn_scan5(const float* __restrict__ Whh, const float* __restrict__ h0) {
    float* Ws = (float*)dynsm;            // [128][8][36]
    float* hb = Ws + HB_OFF;              // [2][8][36]

    const int t    = threadIdx.x;
    const int b    = blockIdx.x;
    const int lane = t & 31;
    const int warp = t >> 5;
    const int o    = warp * 4 + (lane >> 3);   // 0..127
    const int p    = lane & 7;                 // K part (32 cols each)

    // fill SMEM half of W (rows 0..127), part-padded layout
    for (int i = t; i < 128 * 256; i += 1024) {
        int r = i >> 8, c = i & 255;
        Ws[r * WROW + (c >> 5) * 36 + (c & 31)] = Whh[r * 256 + c];
    }
    // register half of W: row 128+o, cols [p*32, p*32+32) as 8 x ulonglong2
    ulonglong2 wr[8];
    {
        const ulonglong2* wsrc = (const ulonglong2*)(Whh + (size_t)(128 + o) * 256 + p * 32);
        #pragma unroll
        for (int i = 0; i < 8; i++) wr[i] = wsrc[i];
    }
    // init h0 into parity-0 buffer (part-padded layout)
    if (t < 256) hb[(t >> 5) * 36 + (t & 31)] = h0[b * 256 + t];

    const bool own = (p < 2);
    const int  c   = (p == 0) ? o : (o + 128);
    const float* xptr = g_Xp + (size_t)b * HIDDEN + c;
    float xcur = own ? __ldg(xptr) : 0.f;
    __syncthreads();

    const ulonglong2* wss = (const ulonglong2*)(Ws + o * WROW + p * 36);

    int par = 0;
    for (int s = 0; s < SEQ; s++) {
        // emit Y row s-1 (tf32-rounded) with idle lanes: t<64, LDS.128 + STG.128
        if (s > 0 && t < 64) {
            const float4 hv4 = *(const float4*)(hb + par * WROW + (t >> 3) * 36 + 4 * (t & 7));
            uint4 u = make_uint4(f2tf32(hv4.x), f2tf32(hv4.y), f2tf32(hv4.z), f2tf32(hv4.w));
            *(uint4*)(g_Y + (size_t)((s - 1) * BATCH + b) * HIDDEN + 4 * t) = u;
        }
        // prefetch next step's x (addresses independent of h)
        float xnxt = 0.f;
        if (own && s + 1 < SEQ) xnxt = __ldg(xptr + (size_t)(s + 1) * BATCH * HIDDEN);

        // partial dot products: smem half (rows 0..127) + register half (128..255)
        const ulonglong2* hsg = (const ulonglong2*)(hb + par * WROW + p * 36);
        uint64_t a0 = 0, a1 = 0;
        #pragma unroll
        for (int j = 0; j < 8; j++) {
            ulonglong2 h2 = hsg[j];      // broadcast across the 4 o's sharing p
            ulonglong2 w2 = wss[j];
            fma2(a0, w2.x, h2.x);
            fma2(a1, wr[j].x, h2.x);
            fma2(a0, w2.y, h2.y);
            fma2(a1, wr[j].y, h2.y);
        }
        float s0 = lo32(a0) + hi32(a0);
        float s1 = lo32(a1) + hi32(a1);
        #pragma unroll
        for (int m = 4; m; m >>= 1) {
            s0 += __shfl_xor_sync(0xffffffffu, s0, m, 8);
            s1 += __shfl_xor_sync(0xffffffffu, s1, m, 8);
        }
        if (own) {
            float pre = ((p == 0) ? s0 : s1) + xcur;
            float hv  = tanhf(pre);
            hb[(par ^ 1) * WROW + (c >> 5) * 36 + (c & 31)] = hv;
            xcur = xnxt;
        }
        __syncthreads();
        par ^= 1;
    }
    // final: Y row SEQ-1 and exact h_last
    if (t < 256) {
        float hv = hb[par * WROW + (t >> 5) * 36 + (t & 31)];
        g_Y[(size_t)((SEQ - 1) * BATCH + b) * HIDDEN + t] = __uint_as_float(f2tf32(hv));
        g_hlast[b * HIDDEN + t] = hv;
    }
}

// ---------------- K3: output GEMM — R4-proven BM128 x BN64 (unchanged) ----------------
// out[r][v] = sum_k Y[r][k] * W_out[v][k] + b_out[v]
// 256 threads, 8 warps as 4(M)x2(N); warp tile 32x32 via m16n8k8; 2-stage cp.async.
#define STG_FLOATS (128 * 36 + 64 * 36)   // 6912 u32 per stage
#define GEMM_SMEM  (2 * STG_FLOATS * 4)   // 55296 bytes

__device__ __forceinline__ void mma_tf32(float* d, const uint32_t* a, const uint32_t* b) {
    asm volatile(
        "mma.sync.aligned.m16n8k8.row.col.f32.tf32.tf32.f32 "
        "{%0,%1,%2,%3}, {%4,%5,%6,%7}, {%8,%9}, {%0,%1,%2,%3};"
        : "+f"(d[0]), "+f"(d[1]), "+f"(d[2]), "+f"(d[3])
        : "r"(a[0]), "r"(a[1]), "r"(a[2]), "r"(a[3]), "r"(b[0]), "r"(b[1]));
}

__global__ __launch_bounds__(256)
void gemm_out(const float* __restrict__ bout, float* __restrict__ out) {
    uint32_t* smbase = (uint32_t*)dynsm;
    const int t = threadIdx.x;
    const int warp = t >> 5, lane = t & 31;
    const int wm = warp & 3, wn = warp >> 2;
    const int r = lane >> 2, c = lane & 3;
    const int rowBase = blockIdx.y * 128;
    const int colBase = blockIdx.x * 64;

    const uint32_t sm0 = smem_u32(smbase);

    float acc[2][4][4];
    #pragma unroll
    for (int mt = 0; mt < 2; mt++)
        #pragma unroll
        for (int nt = 0; nt < 4; nt++)
            #pragma unroll
            for (int i = 0; i < 4; i++) acc[mt][nt][i] = 0.f;

    auto load_stage = [&](int kt, int st) {
        uint32_t abase = sm0 + st * (STG_FLOATS * 4);
        uint32_t bbase = abase + 128 * 36 * 4;
        #pragma unroll
        for (int q = 0; q < 4; q++) {          // A: 128x32 from g_Y
            int lin = q * 256 + t;
            int m = lin >> 3, k4 = lin & 7;
            cpa16(abase + (m * 36 + k4 * 4) * 4,
                  g_Y + (size_t)(rowBase + m) * HIDDEN + kt * 32 + k4 * 4);
        }
        #pragma unroll
        for (int q = 0; q < 2; q++) {          // B: 64x32 from g_Wo
            int lin = q * 256 + t;
            int n = lin >> 3, k4 = lin & 7;
            cpa16(bbase + (n * 36 + k4 * 4) * 4,
                  g_Wo + (size_t)(colBase + n) * HIDDEN + kt * 32 + k4 * 4);
        }
        asm volatile("cp.async.commit_group;");
    };

    load_stage(0, 0);

    for (int kt = 0; kt < 8; kt++) {
        if (kt < 7) {
            load_stage(kt + 1, (kt + 1) & 1);
            asm volatile("cp.async.wait_group 1;");
        } else {
            asm volatile("cp.async.wait_group 0;");
        }
        __syncthreads();

        const uint32_t* As = smbase + (kt & 1) * STG_FLOATS;
        const uint32_t* Bs = As + 128 * 36;

        #pragma unroll
        for (int ks = 0; ks < 4; ks++) {
            uint32_t a[2][4], bf[4][2];
            #pragma unroll
            for (int mt = 0; mt < 2; mt++) {
                int mb = wm * 32 + mt * 16;
                a[mt][0] = As[(mb + r    ) * 36 + ks * 8 + c    ];
                a[mt][1] = As[(mb + r + 8) * 36 + ks * 8 + c    ];
                a[mt][2] = As[(mb + r    ) * 36 + ks * 8 + c + 4];
                a[mt][3] = As[(mb + r + 8) * 36 + ks * 8 + c + 4];
            }
            #pragma unroll
            for (int nt = 0; nt < 4; nt++) {
                int nb = wn * 32 + nt * 8 + r;
                bf[nt][0] = Bs[nb * 36 + ks * 8 + c    ];
                bf[nt][1] = Bs[nb * 36 + ks * 8 + c + 4];
            }
            #pragma unroll
            for (int mt = 0; mt < 2; mt++)
                #pragma unroll
                for (int nt = 0; nt < 4; nt++)
                    mma_tf32(acc[mt][nt], a[mt], bf[nt]);
        }
        __syncthreads();
    }

    // epilogue: add bias, STG.64 pairs (VOCAB % 64 == 0 -> no predication needed)
    #pragma unroll
    for (int mt = 0; mt < 2; mt++) {
        int r0 = rowBase + wm * 32 + mt * 16 + r;
        #pragma unroll
        for (int nt = 0; nt < 4; nt++) {
            int col = colBase + wn * 32 + nt * 8 + c * 2;
            float bo0 = bout[col], bo1 = bout[col + 1];
            float2 v0 = make_float2(acc[mt][nt][0] + bo0, acc[mt][nt][1] + bo1);
            float2 v1 = make_float2(acc[mt][nt][2] + bo0, acc[mt][nt][3] + bo1);
            *(float2*)&out[(size_t)r0       * VOCAB + col] = v0;
            *(float2*)&out[(size_t)(r0 + 8) * VOCAB + col] = v1;
        }
    }
}

// ---------------- K4: h_last tail (exact fp32) ----------------
__global__ void tail_copy(float* __restrict__ out) {
    int t = blockIdx.x * blockDim.x + threadIdx.x;   // 0..8191
    out[(size_t)NROW * VOCAB + t] = g_hlast[t];
}

// ---------------- launch ----------------
extern "C" void kernel_launch(void* const* d_in, const int* in_sizes, int n_in,
                              void* d_out, int out_size) {
    const int*   X     = (const int*)  d_in[0];
    const float* h0    = (const float*)d_in[1];
    const float* W_ih  = (const float*)d_in[2];
    const float* b_ih  = (const float*)d_in[3];
    const float* W_hh  = (const float*)d_in[4];
    const float* b_hh  = (const float*)d_in[5];
    const float* W_out = (const float*)d_in[6];
    const float* b_out = (const float*)d_in[7];
    float* out = (float*)d_out;

    cudaFuncSetAttribute(rnn_scan5, cudaFuncAttributeMaxDynamicSharedMemorySize, RNN_SMEM);
    cudaFuncSetAttribute(gemm_out,  cudaFuncAttributeMaxDynamicSharedMemorySize, GEMM_SMEM);

    transpose_wih<<<dim3(VOCAB / 32, HIDDEN / 32), dim3(32, 8)>>>(W_ih);
    gather_emb<<<(NROW * 64) / 256, 256>>>(X, b_ih, b_hh);
    round_wout<<<(VOCAB * 64) / 256, 256>>>(W_out);
    rnn_scan5<<<BATCH, 1024, RNN_SMEM>>>(W_hh, h0);
    gemm_out<<<dim3(VOCAB / 64, NROW / 128), 256, GEMM_SMEM>>>(b_out, out);
    if ((long long)out_size >= (long long)NROW * VOCAB + BATCH * HIDDEN)
        tail_copy<<<BATCH, HIDDEN>>>(out);
}

// round 9
// speedup vs baseline: 1.1730x; 1.1730x over previous
#include <cuda_runtime.h>
#include <cstdint>

#define VOCAB  8000
#define VPAD   8064               // padded rows in g_Wo (kept; only first VOCAB used)
#define HIDDEN 256
#define BATCH  32
#define SEQ    256
#define NROW   (SEQ * BATCH)      // 8192 output rows

// ---------------- scratch (device globals: allocation-free) ----------------
__device__ float g_WT[VOCAB * HIDDEN];   // W_ih transposed: [vocab][hidden]
__device__ float g_Xp[NROW * HIDDEN];    // gathered emb + b_ih + b_hh, rows = s*BATCH+b
__device__ float g_Y [NROW * HIDDEN];    // RNN hidden outputs (tf32-rounded)
__device__ float g_Wo[VPAD * HIDDEN];    // W_out pre-rounded to tf32
__device__ float g_hlast[BATCH * HIDDEN];// exact fp32 final hidden state

extern __shared__ unsigned char dynsm[];

// ---------------- helpers ----------------
__device__ __forceinline__ uint32_t smem_u32(const void* p) {
    uint32_t a;
    asm("{ .reg .u64 t; cvta.to.shared.u64 t, %1; cvt.u32.u64 %0, t; }"
        : "=r"(a) : "l"(p));
    return a;
}
__device__ __forceinline__ uint32_t f2tf32(float f) {
    uint32_t r; asm("cvt.rna.tf32.f32 %0, %1;" : "=r"(r) : "f"(f)); return r;
}
__device__ __forceinline__ void fma2(uint64_t& d, uint64_t a, uint64_t b) {
    asm("fma.rn.f32x2 %0, %1, %2, %0;" : "+l"(d) : "l"(a), "l"(b));
}
__device__ __forceinline__ float lo32(uint64_t v) { return __uint_as_float((uint32_t)v); }
__device__ __forceinline__ float hi32(uint64_t v) { return __uint_as_float((uint32_t)(v >> 32)); }
__device__ __forceinline__ void cpa16(uint32_t dst, const void* src) {
    asm volatile("cp.async.cg.shared.global [%0], [%1], 16;" :: "r"(dst), "l"(src));
}

// ---------------- K0: transpose W_ih (HIDDEN x VOCAB) -> g_WT ----------------
__global__ void transpose_wih(const float* __restrict__ W) {
    __shared__ float tile[32][33];
    int vx = blockIdx.x * 32 + threadIdx.x;
    int ib = blockIdx.y * 32;
    #pragma unroll
    for (int k = 0; k < 32; k += 8) {
        int i = ib + threadIdx.y + k;
        tile[threadIdx.y + k][threadIdx.x] = W[(size_t)i * VOCAB + vx];
    }
    __syncthreads();
    int i = ib + threadIdx.x;
    #pragma unroll
    for (int k = 0; k < 32; k += 8) {
        int v = blockIdx.x * 32 + threadIdx.y + k;
        g_WT[(size_t)v * HIDDEN + i] = tile[threadIdx.x][threadIdx.y + k];
    }
}

// ---------------- K1: gather embedding + fold both biases ----------------
__global__ void gather_emb(const int* __restrict__ X,
                           const float* __restrict__ b_ih,
                           const float* __restrict__ b_hh) {
    int idx = blockIdx.x * blockDim.x + threadIdx.x;
    int r = idx >> 6, q = idx & 63;
    int s = r >> 5, b = r & 31;
    int v = X[b * SEQ + s];
    float4 e  = ((const float4*)g_WT)[(size_t)v * 64 + q];
    float4 bi = ((const float4*)b_ih)[q];
    float4 bh = ((const float4*)b_hh)[q];
    e.x += bi.x + bh.x;  e.y += bi.y + bh.y;
    e.z += bi.z + bh.z;  e.w += bi.w + bh.w;
    ((float4*)g_Xp)[(size_t)r * 64 + q] = e;
}

// ---------------- K1b: pre-round W_out to tf32 ----------------
__global__ void round_wout(const float* __restrict__ Wout) {
    int i = blockIdx.x * blockDim.x + threadIdx.x;  // over VOCAB*64 float4s
    float4 f = ((const float4*)Wout)[i];
    uint4 u = make_uint4(f2tf32(f.x), f2tf32(f.y), f2tf32(f.z), f2tf32(f.w));
    ((uint4*)g_Wo)[i] = u;
}

// ---------------- K2: RNN scan v6 — scan2 structure (best measured), LDS.128 diet --------
// 32 CTAs (one batch each), 1024 threads. o = t&127 (warp = 32 consecutive o),
// p = t>>7 (whole warp shares one K-part -> every h load is a full-warp
// broadcast, 1 wavefront). W smem half rows 0..127 at stride 260 words
// (260 mod 32 = 4 -> the 8-lane LDS.128 phase hits banks 4o..4o+3, tiling all
// 32 banks: conflict-free). Reg half rows 128..255 (32 regs). Split-K reduce
// via part[] smem + phase B (no shfl chains). Two barriers per step.
#define WSTR      260
#define HB_OFF    (128 * WSTR)                  // hbuf: [2][256]
#define PART_OFF  (HB_OFF + 512)                // part: [16][132]
#define XBUF_OFF  (PART_OFF + 2112)             // xbuf: [256]
#define RNN_SMEM  ((XBUF_OFF + 256) * 4)        // 144,640 B

__global__ void __launch_bounds__(1024, 1)
rnn_scan6(const float* __restrict__ Whh, const float* __restrict__ h0) {
    float* Ws   = (float*)dynsm;          // [128][260]
    float* hbuf = Ws + HB_OFF;            // [2][256]
    float* part = Ws + PART_OFF;          // [16][132]
    float* xbuf = Ws + XBUF_OFF;          // [256]

    const int t = threadIdx.x;
    const int b = blockIdx.x;
    const int o = t & 127;                // output row within half
    const int p = t >> 7;                 // K part (32 cols each), uniform per warp

    // fill SMEM half of W (rows 0..127), stride-260
    for (int i = t; i < 128 * 256; i += 1024) {
        int r = i >> 8, c = i & 255;
        Ws[r * WSTR + c] = Whh[r * 256 + c];
    }
    // register half of W: row 128+o, cols [p*32, p*32+32) as 8 x ulonglong2
    ulonglong2 wr[8];
    {
        const ulonglong2* wsrc = (const ulonglong2*)(Whh + (size_t)(128 + o) * 256 + p * 32);
        #pragma unroll
        for (int i = 0; i < 8; i++) wr[i] = wsrc[i];
    }
    if (t < 256) hbuf[t] = h0[b * 256 + t];
    __syncthreads();

    // o*260 words = 1040*o bytes (16B-aligned); p*32 words = 128*p bytes: ul2-safe
    const ulonglong2* wss = (const ulonglong2*)(Ws + o * WSTR + p * 32);

    int par = 0;
    for (int s = 0; s < SEQ; s++) {
        // prefetch this step's x row (LDG latency hidden under phase A)
        float4 xv;
        if (t < 64) xv = ((const float4*)(g_Xp + (size_t)(s * BATCH + b) * HIDDEN))[t];

        // phase A: partial dot products (smem half + register half)
        const ulonglong2* hsg = ((const ulonglong2*)(hbuf + par * 256)) + p * 8;
        uint64_t accs = 0, accr = 0;
        #pragma unroll
        for (int j = 0; j < 8; j++) {
            ulonglong2 h2 = hsg[j];       // full-warp broadcast
            ulonglong2 w2 = wss[j];
            fma2(accs, w2.x, h2.x);
            fma2(accr, wr[j].x, h2.x);
            fma2(accs, w2.y, h2.y);
            fma2(accr, wr[j].y, h2.y);
        }
        part[p * 132 + o]       = lo32(accs) + hi32(accs);   // rows 0..127
        part[(8 + p) * 132 + o] = lo32(accr) + hi32(accr);   // rows 128..255
        if (t < 64) ((float4*)xbuf)[t] = xv;
        __syncthreads();

        // phase B: reduce 8 partials, add x, tanh, update h, emit Y (tf32)
        if (t < 256) {
            int w = t >> 7, oo = t & 127;
            float sum = 0.f;
            #pragma unroll
            for (int q = 0; q < 8; q++) sum += part[(w * 8 + q) * 132 + oo];
            float v = tanhf(sum + xbuf[t]);
            hbuf[(par ^ 1) * 256 + t] = v;
            g_Y[(size_t)(s * BATCH + b) * HIDDEN + t] = __uint_as_float(f2tf32(v));
            if (s == SEQ - 1) g_hlast[b * HIDDEN + t] = v;
        }
        __syncthreads();
        par ^= 1;
    }
}

// ---------------- K3: output GEMM — R4-proven BM128 x BN64 (unchanged) ----------------
// out[r][v] = sum_k Y[r][k] * W_out[v][k] + b_out[v]
// 256 threads, 8 warps as 4(M)x2(N); warp tile 32x32 via m16n8k8; 2-stage cp.async.
#define STG_FLOATS (128 * 36 + 64 * 36)   // 6912 u32 per stage
#define GEMM_SMEM  (2 * STG_FLOATS * 4)   // 55296 bytes

__device__ __forceinline__ void mma_tf32(float* d, const uint32_t* a, const uint32_t* b) {
    asm volatile(
        "mma.sync.aligned.m16n8k8.row.col.f32.tf32.tf32.f32 "
        "{%0,%1,%2,%3}, {%4,%5,%6,%7}, {%8,%9}, {%0,%1,%2,%3};"
        : "+f"(d[0]), "+f"(d[1]), "+f"(d[2]), "+f"(d[3])
        : "r"(a[0]), "r"(a[1]), "r"(a[2]), "r"(a[3]), "r"(b[0]), "r"(b[1]));
}

__global__ __launch_bounds__(256)
void gemm_out(const float* __restrict__ bout, float* __restrict__ out) {
    uint32_t* smbase = (uint32_t*)dynsm;
    const int t = threadIdx.x;
    const int warp = t >> 5, lane = t & 31;
    const int wm = warp & 3, wn = warp >> 2;
    const int r = lane >> 2, c = lane & 3;
    const int rowBase = blockIdx.y * 128;
    const int colBase = blockIdx.x * 64;

    const uint32_t sm0 = smem_u32(smbase);

    float acc[2][4][4];
    #pragma unroll
    for (int mt = 0; mt < 2; mt++)
        #pragma unroll
        for (int nt = 0; nt < 4; nt++)
            #pragma unroll
            for (int i = 0; i < 4; i++) acc[mt][nt][i] = 0.f;

    auto load_stage = [&](int kt, int st) {
        uint32_t abase = sm0 + st * (STG_FLOATS * 4);
        uint32_t bbase = abase + 128 * 36 * 4;
        #pragma unroll
        for (int q = 0; q < 4; q++) {          // A: 128x32 from g_Y
            int lin = q * 256 + t;
            int m = lin >> 3, k4 = lin & 7;
            cpa16(abase + (m * 36 + k4 * 4) * 4,
                  g_Y + (size_t)(rowBase + m) * HIDDEN + kt * 32 + k4 * 4);
        }
        #pragma unroll
        for (int q = 0; q < 2; q++) {          // B: 64x32 from g_Wo
            int lin = q * 256 + t;
            int n = lin >> 3, k4 = lin & 7;
            cpa16(bbase + (n * 36 + k4 * 4) * 4,
                  g_Wo + (size_t)(colBase + n) * HIDDEN + kt * 32 + k4 * 4);
        }
        asm volatile("cp.async.commit_group;");
    };

    load_stage(0, 0);

    for (int kt = 0; kt < 8; kt++) {
        if (kt < 7) {
            load_stage(kt + 1, (kt + 1) & 1);
            asm volatile("cp.async.wait_group 1;");
        } else {
            asm volatile("cp.async.wait_group 0;");
        }
        __syncthreads();

        const uint32_t* As = smbase + (kt & 1) * STG_FLOATS;
        const uint32_t* Bs = As + 128 * 36;

        #pragma unroll
        for (int ks = 0; ks < 4; ks++) {
            uint32_t a[2][4], bf[4][2];
            #pragma unroll
            for (int mt = 0; mt < 2; mt++) {
                int mb = wm * 32 + mt * 16;
                a[mt][0] = As[(mb + r    ) * 36 + ks * 8 + c    ];
                a[mt][1] = As[(mb + r + 8) * 36 + ks * 8 + c    ];
                a[mt][2] = As[(mb + r    ) * 36 + ks * 8 + c + 4];
                a[mt][3] = As[(mb + r + 8) * 36 + ks * 8 + c + 4];
            }
            #pragma unroll
            for (int nt = 0; nt < 4; nt++) {
                int nb = wn * 32 + nt * 8 + r;
                bf[nt][0] = Bs[nb * 36 + ks * 8 + c    ];
                bf[nt][1] = Bs[nb * 36 + ks * 8 + c + 4];
            }
            #pragma unroll
            for (int mt = 0; mt < 2; mt++)
                #pragma unroll
                for (int nt = 0; nt < 4; nt++)
                    mma_tf32(acc[mt][nt], a[mt], bf[nt]);
        }
        __syncthreads();
    }

    // epilogue: add bias, STG.64 pairs (VOCAB % 64 == 0 -> no predication needed)
    #pragma unroll
    for (int mt = 0; mt < 2; mt++) {
        int r0 = rowBase + wm * 32 + mt * 16 + r;
        #pragma unroll
        for (int nt = 0; nt < 4; nt++) {
            int col = colBase + wn * 32 + nt * 8 + c * 2;
            float bo0 = bout[col], bo1 = bout[col + 1];
            float2 v0 = make_float2(acc[mt][nt][0] + bo0, acc[mt][nt][1] + bo1);
            float2 v1 = make_float2(acc[mt][nt][2] + bo0, acc[mt][nt][3] + bo1);
            *(float2*)&out[(size_t)r0       * VOCAB + col] = v0;
            *(float2*)&out[(size_t)(r0 + 8) * VOCAB + col] = v1;
        }
    }
}

// ---------------- K4: h_last tail (exact fp32) ----------------
__global__ void tail_copy(float* __restrict__ out) {
    int t = blockIdx.x * blockDim.x + threadIdx.x;   // 0..8191
    out[(size_t)NROW * VOCAB + t] = g_hlast[t];
}

// ---------------- launch ----------------
extern "C" void kernel_launch(void* const* d_in, const int* in_sizes, int n_in,
                              void* d_out, int out_size) {
    const int*   X     = (const int*)  d_in[0];
    const float* h0    = (const float*)d_in[1];
    const float* W_ih  = (const float*)d_in[2];
    const float* b_ih  = (const float*)d_in[3];
    const float* W_hh  = (const float*)d_in[4];
    const float* b_hh  = (const float*)d_in[5];
    const float* W_out = (const float*)d_in[6];
    const float* b_out = (const float*)d_in[7];
    float* out = (float*)d_out;

    cudaFuncSetAttribute(rnn_scan6, cudaFuncAttributeMaxDynamicSharedMemorySize, RNN_SMEM);
    cudaFuncSetAttribute(gemm_out,  cudaFuncAttributeMaxDynamicSharedMemorySize, GEMM_SMEM);

    transpose_wih<<<dim3(VOCAB / 32, HIDDEN / 32), dim3(32, 8)>>>(W_ih);
    gather_emb<<<(NROW * 64) / 256, 256>>>(X, b_ih, b_hh);
    round_wout<<<(VOCAB * 64) / 256, 256>>>(W_out);
    rnn_scan6<<<BATCH, 1024, RNN_SMEM>>>(W_hh, h0);
    gemm_out<<<dim3(VOCAB / 64, NROW / 128), 256, GEMM_SMEM>>>(b_out, out);
    if ((long long)out_size >= (long long)NROW * VOCAB + BATCH * HIDDEN)
        tail_copy<<<BATCH, HIDDEN>>>(out);
}

// round 10
// speedup vs baseline: 1.3734x; 1.1708x over previous
#include <cuda_runtime.h>
#include <cstdint>

#define VOCAB  8000
#define VPAD   8192               // g_Wo rows padded to multiple of 128 (zero-filled)
#define HIDDEN 256
#define BATCH  32
#define SEQ    256
#define NROW   (SEQ * BATCH)      // 8192 output rows

// ---------------- scratch (device globals: allocation-free) ----------------
__device__ float g_WT[VOCAB * HIDDEN];   // W_ih transposed: [vocab][hidden]
__device__ float g_Xp[NROW * HIDDEN];    // gathered emb + b_ih + b_hh
__device__ float g_Y [NROW * HIDDEN];    // RNN hidden outputs (tf32-rounded)
__device__ float g_Wo[VPAD * HIDDEN];    // W_out pre-rounded to tf32, zero-padded
__device__ float g_hlast[BATCH * HIDDEN];// exact fp32 final hidden state
__device__ unsigned int g_prog[BATCH];   // per-batch completed-step counter

extern __shared__ unsigned char dynsm[];

// ---------------- helpers ----------------
__device__ __forceinline__ uint32_t smem_u32(const void* p) {
    uint32_t a;
    asm("{ .reg .u64 t; cvta.to.shared.u64 t, %1; cvt.u32.u64 %0, t; }"
        : "=r"(a) : "l"(p));
    return a;
}
__device__ __forceinline__ uint32_t f2tf32(float f) {
    uint32_t r; asm("cvt.rna.tf32.f32 %0, %1;" : "=r"(r) : "f"(f)); return r;
}
__device__ __forceinline__ void fma2(uint64_t& d, uint64_t a, uint64_t b) {
    asm("fma.rn.f32x2 %0, %1, %2, %0;" : "+l"(d) : "l"(a), "l"(b));
}
__device__ __forceinline__ float lo32(uint64_t v) { return __uint_as_float((uint32_t)v); }
__device__ __forceinline__ float hi32(uint64_t v) { return __uint_as_float((uint32_t)(v >> 32)); }
__device__ __forceinline__ void cpa16(uint32_t dst, const void* src) {
    asm volatile("cp.async.cg.shared.global [%0], [%1], 16;" :: "r"(dst), "l"(src));
}
__device__ __forceinline__ unsigned int ld_acq(const unsigned int* p) {
    unsigned int v;
    asm volatile("ld.acquire.gpu.u32 %0, [%1];" : "=r"(v) : "l"(p) : "memory");
    return v;
}
__device__ __forceinline__ void st_rlx(unsigned int* p, unsigned int v) {
    asm volatile("st.relaxed.gpu.u32 [%0], %1;" :: "l"(p), "r"(v) : "memory");
}

// ---------------- K0: transpose W_ih (HIDDEN x VOCAB) -> g_WT ----------------
__global__ void transpose_wih(const float* __restrict__ W) {
    __shared__ float tile[32][33];
    int vx = blockIdx.x * 32 + threadIdx.x;
    int ib = blockIdx.y * 32;
    #pragma unroll
    for (int k = 0; k < 32; k += 8) {
        int i = ib + threadIdx.y + k;
        tile[threadIdx.y + k][threadIdx.x] = W[(size_t)i * VOCAB + vx];
    }
    __syncthreads();
    int i = ib + threadIdx.x;
    #pragma unroll
    for (int k = 0; k < 32; k += 8) {
        int v = blockIdx.x * 32 + threadIdx.y + k;
        g_WT[(size_t)v * HIDDEN + i] = tile[threadIdx.x][threadIdx.y + k];
    }
}

// ---------------- K1: gather embedding + fold both biases ----------------
__global__ void gather_emb(const int* __restrict__ X,
                           const float* __restrict__ b_ih,
                           const float* __restrict__ b_hh) {
    int idx = blockIdx.x * blockDim.x + threadIdx.x;
    int r = idx >> 6, q = idx & 63;
    int s = r >> 5, b = r & 31;
    int v = X[b * SEQ + s];
    float4 e  = ((const float4*)g_WT)[(size_t)v * 64 + q];
    float4 bi = ((const float4*)b_ih)[q];
    float4 bh = ((const float4*)b_hh)[q];
    e.x += bi.x + bh.x;  e.y += bi.y + bh.y;
    e.z += bi.z + bh.z;  e.w += bi.w + bh.w;
    ((float4*)g_Xp)[(size_t)r * 64 + q] = e;
}

// ---------------- K1b: pre-round W_out to tf32 (zero-pad rows >= VOCAB); zero prog ------
__global__ void round_wout(const float* __restrict__ Wout) {
    int i = blockIdx.x * blockDim.x + threadIdx.x;  // over VPAD*64 float4s
    if (blockIdx.x == 0 && threadIdx.x < BATCH) g_prog[threadIdx.x] = 0;
    int row = i >> 6;
    uint4 u = make_uint4(0u, 0u, 0u, 0u);
    if (row < VOCAB) {
        float4 f = ((const float4*)Wout)[i];
        u = make_uint4(f2tf32(f.x), f2tf32(f.y), f2tf32(f.z), f2tf32(f.w));
    }
    ((uint4*)g_Wo)[i] = u;
}

// ---------------- K2: FUSED scan + GEMM (persistent overlap) ----------------
// Blocks 0..31: rnn scan (scan6 verbatim) for batch b = blockIdx.x, publishing
//   g_prog[b] = s+1 every 4 steps (threadfence by writers -> bar -> relaxed st).
// Blocks 32..: GEMM BM128 x BN128 row-tile-major; block waits until all 32
//   batches have completed the 4 steps feeding its row tile, then computes.
// Scan blocks are FIRST in the grid -> wave 1 (deterministic classic-launch
// placement) always contains all producers: no deadlock.
#define WSTR      260
#define HB_OFF    (128 * WSTR)                  // hbuf: [2][256]
#define PART_OFF  (HB_OFF + 512)                // part: [16][132]
#define XBUF_OFF  (PART_OFF + 2112)             // xbuf: [256]
#define FUSED_SMEM ((XBUF_OFF + 256) * 4)       // 144,640 B (gemm uses 73,728)

// gemm tiling inside fused kernel: 1024 threads = 32 warps as 4(M) x 8(N),
// warp tile 32x16 -> acc[2][2][4] = 16 regs (fits 64-reg cap @ 1024 thr).
#define GSTG  (128 * 36 + 128 * 36)             // 9216 u32 per stage

__device__ __forceinline__ void mma_tf32(float* d, const uint32_t* a, const uint32_t* b) {
    asm volatile(
        "mma.sync.aligned.m16n8k8.row.col.f32.tf32.tf32.f32 "
        "{%0,%1,%2,%3}, {%4,%5,%6,%7}, {%8,%9}, {%0,%1,%2,%3};"
        : "+f"(d[0]), "+f"(d[1]), "+f"(d[2]), "+f"(d[3])
        : "r"(a[0]), "r"(a[1]), "r"(a[2]), "r"(a[3]), "r"(b[0]), "r"(b[1]));
}

__global__ void __launch_bounds__(1024, 1)
fused_scan_gemm(const float* __restrict__ Whh, const float* __restrict__ h0,
                const float* __restrict__ bout, float* __restrict__ out) {
    const int t = threadIdx.x;

    if (blockIdx.x < 32) {
        // ================= scan (scan6, proven 264us) =================
        float* Ws   = (float*)dynsm;          // [128][260]
        float* hbuf = Ws + HB_OFF;            // [2][256]
        float* part = Ws + PART_OFF;          // [16][132]
        float* xbuf = Ws + XBUF_OFF;          // [256]

        const int b = blockIdx.x;
        const int o = t & 127;
        const int p = t >> 7;

        for (int i = t; i < 128 * 256; i += 1024) {
            int r = i >> 8, c = i & 255;
            Ws[r * WSTR + c] = Whh[r * 256 + c];
        }
        ulonglong2 wr[8];
        {
            const ulonglong2* wsrc = (const ulonglong2*)(Whh + (size_t)(128 + o) * 256 + p * 32);
            #pragma unroll
            for (int i = 0; i < 8; i++) wr[i] = wsrc[i];
        }
        if (t < 256) hbuf[t] = h0[b * 256 + t];
        __syncthreads();

        const ulonglong2* wss = (const ulonglong2*)(Ws + o * WSTR + p * 32);

        int par = 0;
        for (int s = 0; s < SEQ; s++) {
            float4 xv;
            if (t < 64) xv = ((const float4*)(g_Xp + (size_t)(s * BATCH + b) * HIDDEN))[t];

            const ulonglong2* hsg = ((const ulonglong2*)(hbuf + par * 256)) + p * 8;
            uint64_t accs = 0, accr = 0;
            #pragma unroll
            for (int j = 0; j < 8; j++) {
                ulonglong2 h2 = hsg[j];
                ulonglong2 w2 = wss[j];
                fma2(accs, w2.x, h2.x);
                fma2(accr, wr[j].x, h2.x);
                fma2(accs, w2.y, h2.y);
                fma2(accr, wr[j].y, h2.y);
            }
            part[p * 132 + o]       = lo32(accs) + hi32(accs);
            part[(8 + p) * 132 + o] = lo32(accr) + hi32(accr);
            if (t < 64) ((float4*)xbuf)[t] = xv;
            __syncthreads();

            if (t < 256) {
                int w = t >> 7, oo = t & 127;
                float sum = 0.f;
                #pragma unroll
                for (int q = 0; q < 8; q++) sum += part[(w * 8 + q) * 132 + oo];
                float v = tanhf(sum + xbuf[t]);
                hbuf[(par ^ 1) * 256 + t] = v;
                g_Y[(size_t)(s * BATCH + b) * HIDDEN + t] = __uint_as_float(f2tf32(v));
                if (s == SEQ - 1) g_hlast[b * HIDDEN + t] = v;
                if ((s & 3) == 3) __threadfence();   // release Y rows before publish
            }
            __syncthreads();
            if ((s & 3) == 3 && t == 0) st_rlx(&g_prog[b], (unsigned int)(s + 1));
            par ^= 1;
        }
    } else {
        // ================= gemm consumer =================
        uint32_t* smbase = (uint32_t*)dynsm;
        const int g = blockIdx.x - 32;
        const int rTile = g >> 6;             // row-tile-major: early blocks need early steps
        const int cTile = g & 63;
        const int rowBase = rTile * 128;
        const int colBase = cTile * 128;
        const unsigned int need = (unsigned int)((rTile + 1) * 4);

        // wait until every batch has completed the steps feeding this row tile
        if (t < 32) {
            while (ld_acq(&g_prog[t]) < need) __nanosleep(128);
        }
        __syncthreads();

        const int warp = t >> 5, lane = t & 31;
        const int wm = warp & 3, wn = warp >> 2;      // 4(M) x 8(N)
        const int r = lane >> 2, c = lane & 3;
        const uint32_t sm0 = smem_u32(smbase);

        float acc[2][2][4];
        #pragma unroll
        for (int mt = 0; mt < 2; mt++)
            #pragma unroll
            for (int nt = 0; nt < 2; nt++)
                #pragma unroll
                for (int i = 0; i < 4; i++) acc[mt][nt][i] = 0.f;

        auto load_stage = [&](int kt, int st) {
            uint32_t abase = sm0 + st * (GSTG * 4);
            uint32_t bbase = abase + 128 * 36 * 4;
            {   // A: 128x32 from g_Y — 1 cpa16 per thread
                int m = t >> 3, k4 = t & 7;
                cpa16(abase + (m * 36 + k4 * 4) * 4,
                      g_Y + (size_t)(rowBase + m) * HIDDEN + kt * 32 + k4 * 4);
            }
            {   // B: 128x32 from g_Wo — 1 cpa16 per thread
                int n = t >> 3, k4 = t & 7;
                cpa16(bbase + (n * 36 + k4 * 4) * 4,
                      g_Wo + (size_t)(colBase + n) * HIDDEN + kt * 32 + k4 * 4);
            }
            asm volatile("cp.async.commit_group;");
        };

        load_stage(0, 0);

        for (int kt = 0; kt < 8; kt++) {
            if (kt < 7) {
                load_stage(kt + 1, (kt + 1) & 1);
                asm volatile("cp.async.wait_group 1;");
            } else {
                asm volatile("cp.async.wait_group 0;");
            }
            __syncthreads();

            const uint32_t* As = smbase + (kt & 1) * GSTG;
            const uint32_t* Bs = As + 128 * 36;

            #pragma unroll
            for (int ks = 0; ks < 4; ks++) {
                uint32_t a[2][4], bf[2][2];
                #pragma unroll
                for (int mt = 0; mt < 2; mt++) {
                    int mb = wm * 32 + mt * 16;
                    a[mt][0] = As[(mb + r    ) * 36 + ks * 8 + c    ];
                    a[mt][1] = As[(mb + r + 8) * 36 + ks * 8 + c    ];
                    a[mt][2] = As[(mb + r    ) * 36 + ks * 8 + c + 4];
                    a[mt][3] = As[(mb + r + 8) * 36 + ks * 8 + c + 4];
                }
                #pragma unroll
                for (int nt = 0; nt < 2; nt++) {
                    int nb = wn * 16 + nt * 8 + r;
                    bf[nt][0] = Bs[nb * 36 + ks * 8 + c    ];
                    bf[nt][1] = Bs[nb * 36 + ks * 8 + c + 4];
                }
                #pragma unroll
                for (int mt = 0; mt < 2; mt++)
                    #pragma unroll
                    for (int nt = 0; nt < 2; nt++)
                        mma_tf32(acc[mt][nt], a[mt], bf[nt]);
            }
            __syncthreads();
        }

        // epilogue: bias + predicated STG.64 (cols >= VOCAB are padding)
        #pragma unroll
        for (int mt = 0; mt < 2; mt++) {
            int r0 = rowBase + wm * 32 + mt * 16 + r;
            #pragma unroll
            for (int nt = 0; nt < 2; nt++) {
                int col = colBase + wn * 16 + nt * 8 + c * 2;
                if (col < VOCAB) {
                    float bo0 = bout[col], bo1 = bout[col + 1];
                    float2 v0 = make_float2(acc[mt][nt][0] + bo0, acc[mt][nt][1] + bo1);
                    float2 v1 = make_float2(acc[mt][nt][2] + bo0, acc[mt][nt][3] + bo1);
                    *(float2*)&out[(size_t)r0       * VOCAB + col] = v0;
                    *(float2*)&out[(size_t)(r0 + 8) * VOCAB + col] = v1;
                }
            }
        }
    }
}

// ---------------- K4: h_last tail (exact fp32) ----------------
__global__ void tail_copy(float* __restrict__ out) {
    int t = blockIdx.x * blockDim.x + threadIdx.x;   // 0..8191
    out[(size_t)NROW * VOCAB + t] = g_hlast[t];
}

// ---------------- launch ----------------
extern "C" void kernel_launch(void* const* d_in, const int* in_sizes, int n_in,
                              void* d_out, int out_size) {
    const int*   X     = (const int*)  d_in[0];
    const float* h0    = (const float*)d_in[1];
    const float* W_ih  = (const float*)d_in[2];
    const float* b_ih  = (const float*)d_in[3];
    const float* W_hh  = (const float*)d_in[4];
    const float* b_hh  = (const float*)d_in[5];
    const float* W_out = (const float*)d_in[6];
    const float* b_out = (const float*)d_in[7];
    float* out = (float*)d_out;

    cudaFuncSetAttribute(fused_scan_gemm, cudaFuncAttributeMaxDynamicSharedMemorySize, FUSED_SMEM);

    transpose_wih<<<dim3(VOCAB / 32, HIDDEN / 32), dim3(32, 8)>>>(W_ih);
    gather_emb<<<(NROW * 64) / 256, 256>>>(X, b_ih, b_hh);
    round_wout<<<(VPAD * 64) / 256, 256>>>(W_out);
    // 32 scan blocks first, then 64x64 gemm tiles (row-tile-major)
    fused_scan_gemm<<<32 + 64 * 64, 1024, FUSED_SMEM>>>(W_hh, h0, b_out, out);
    if ((long long)out_size >= (long long)NROW * VOCAB + BATCH * HIDDEN)
        tail_copy<<<BATCH, HIDDEN>>>(out);
}